// round 1
// baseline (speedup 1.0000x reference)
#include <cuda_runtime.h>

// Problem constants (fixed shapes: B=16, C=256, H=W=80)
#define L_LEN   6400
#define NTH     256
#define CHUNK   25            // L_LEN / NTH
#define C_CH    256
#define ALPHA_F 0.1f
#define EPS_F   1e-7f

// Per-launch recomputed tables (deterministic). __device__ globals = legal scratch.
__device__ float g_wd[L_LEN];   // alpha * 0.9^j  (float32, matches ref within ~4e-5 rel)
__device__ float g_inv[L_LEN];  // 1 / (cumsum(alpha*0.9^j) + eps)

// Block-wide exclusive scan over 256 threads (8 warps). Contains 2 barriers.
__device__ __forceinline__ float block_excl_scan(float v, int tid) {
    __shared__ float warp_sums[8];
    const int lane = tid & 31;
    const int wid  = tid >> 5;

    // inclusive warp scan
    float inc = v;
    #pragma unroll
    for (int off = 1; off < 32; off <<= 1) {
        float y = __shfl_up_sync(0xffffffffu, inc, off);
        if (lane >= off) inc += y;
    }
    if (lane == 31) warp_sums[wid] = inc;
    __syncthreads();
    if (tid == 0) {
        float s = 0.f;
        #pragma unroll
        for (int w = 0; w < 8; w++) { float t = warp_sums[w]; warp_sums[w] = s; s += t; }
    }
    __syncthreads();
    return warp_sums[wid] + inc - v;   // exclusive prefix for this thread
}

__global__ void ema_setup_kernel() {
    const int t  = threadIdx.x;
    const int i0 = t * CHUNK;
    float ad[CHUNK];
    float s = 0.f;
    #pragma unroll
    for (int k = 0; k < CHUNK; k++) {
        float d = powf(0.9f, (float)(i0 + k));   // decay, fp32 (tiny err vs fp64 ref)
        ad[k] = ALPHA_F * d;
        s += ad[k];
    }
    float run = block_excl_scan(s, t);
    #pragma unroll
    for (int k = 0; k < CHUNK; k++) {
        run += ad[k];
        g_wd[i0 + k]  = ad[k];
        g_inv[i0 + k] = 1.0f / (run + EPS_F);
    }
}

__global__ void __launch_bounds__(NTH)
ema_main_kernel(const float* __restrict__ x,
                const float* __restrict__ conv_w,
                const float* __restrict__ conv_b,
                float* __restrict__ out) {
    __shared__ __align__(16) float xs[L_LEN];

    const int row = blockIdx.x;              // row = b*C + c
    const int c   = row & (C_CH - 1);
    const int t   = threadIdx.x;

    const float* __restrict__ xr   = x   + (size_t)row * L_LEN;
    float*       __restrict__ outr = out + (size_t)row * L_LEN;

    // coalesced float4 load gmem -> smem
    const float4* x4  = reinterpret_cast<const float4*>(xr);
    float4*       xs4 = reinterpret_cast<float4*>(xs);
    #pragma unroll
    for (int i = t; i < L_LEN / 4; i += NTH) xs4[i] = x4[i];
    __syncthreads();

    const int i0 = t * CHUNK;

    // Phase A: per-chunk sum of weighted terms
    float s = 0.f;
    #pragma unroll 5
    for (int k = 0; k < CHUNK; k++)
        s += xs[i0 + k] * __ldg(&g_wd[i0 + k]);

    // Capture boundary neighbors + own first element BEFORE the scan's barriers;
    // after the scan barrier we may overwrite smem in place safely.
    const float leftN  = (t == 0)       ? 0.f : xs[i0 - 1];
    const float rightN = (t == NTH - 1) ? 0.f : xs[i0 + CHUNK];
    float xcur = xs[i0];

    const float w0   = __ldg(&conv_w[c * 3 + 0]);
    const float w1   = __ldg(&conv_w[c * 3 + 1]);
    const float w2   = __ldg(&conv_w[c * 3 + 2]);
    const float bias = __ldg(&conv_b[c]);

    float run = block_excl_scan(s, t);   // barrier: all neighbor reads done chip-wide

    // Phase B: ema + depthwise conv + residual, overwriting own smem chunk in place.
    float xprev = leftN;
    #pragma unroll 5
    for (int k = 0; k < CHUNK; k++) {
        const int i = i0 + k;
        float xnext = (k == CHUNK - 1) ? rightN : xs[i + 1];  // read-ahead before write
        run += xcur * __ldg(&g_wd[i]);
        float ema  = run * __ldg(&g_inv[i]);
        float conv = fmaf(w0, xprev, fmaf(w1, xcur, fmaf(w2, xnext, bias)));
        xs[i] = xcur + ema + conv;
        xprev = xcur;
        xcur  = xnext;
    }
    __syncthreads();

    // coalesced float4 store smem -> gmem
    float4* o4 = reinterpret_cast<float4*>(outr);
    #pragma unroll
    for (int i = t; i < L_LEN / 4; i += NTH) o4[i] = xs4[i];
}

extern "C" void kernel_launch(void* const* d_in, const int* in_sizes, int n_in,
                              void* d_out, int out_size) {
    const float* x      = (const float*)d_in[0];  // [16,256,80,80]
    const float* conv_w = (const float*)d_in[1];  // [256,1,3]
    const float* conv_b = (const float*)d_in[2];  // [256]
    float* out = (float*)d_out;

    ema_setup_kernel<<<1, NTH>>>();
    ema_main_kernel<<<16 * C_CH, NTH>>>(x, conv_w, conv_b, out);
}

// round 2
// speedup vs baseline: 3.9517x; 3.9517x over previous
#include <cuda_runtime.h>

// Fixed shapes: B=16, C=256, H=W=80 -> L=6400 per (b,c) row, 4096 rows.
#define L_LEN    6400
#define NTH      320          // threads per row-CTA
#define CHUNK    20           // L_LEN / NTH, float4-aligned (20*4B = 80B, 16B-aligned)
#define NWARPS   10
#define C_CH     256
#define ALPHA_F  0.1f
#define EPS_F    1e-7f

// Setup tables (recomputed every launch; __device__ globals = legal scratch).
__device__ float g_inv[L_LEN];   // 1 / (cumsum(alpha*0.9^j) + eps)
__device__ float g_w0[NTH];      // alpha * 0.9^(20*t)  (chunk-start anchors)

// ---------------- setup: build g_inv (exact cumsum) and g_w0 anchors ----------------
#define SNTH   256
#define SCHUNK 25
__device__ __forceinline__ float setup_excl_scan(float v, int tid) {
    __shared__ float ws[8];
    const int lane = tid & 31, wid = tid >> 5;
    float inc = v;
    #pragma unroll
    for (int off = 1; off < 32; off <<= 1) {
        float y = __shfl_up_sync(0xffffffffu, inc, off);
        if (lane >= off) inc += y;
    }
    if (lane == 31) ws[wid] = inc;
    __syncthreads();
    if (tid == 0) {
        float s = 0.f;
        #pragma unroll
        for (int w = 0; w < 8; w++) { float t = ws[w]; ws[w] = s; s += t; }
    }
    __syncthreads();
    return ws[wid] + inc - v;
}

__global__ void ema_setup_kernel() {
    const int t = threadIdx.x;
    const int i0 = t * SCHUNK;
    float ad[SCHUNK];
    float s = 0.f;
    #pragma unroll
    for (int k = 0; k < SCHUNK; k++) {
        ad[k] = ALPHA_F * powf(0.9f, (float)(i0 + k));
        s += ad[k];
    }
    float run = setup_excl_scan(s, t);
    #pragma unroll
    for (int k = 0; k < SCHUNK; k++) {
        run += ad[k];
        g_inv[i0 + k] = 1.0f / (run + EPS_F);
    }
    // chunk-start weight anchors for the main kernel
    for (int j = t; j < NTH; j += SNTH)
        g_w0[j] = ALPHA_F * powf(0.9f, (float)(CHUNK * j));
}

// ---------------- main kernel: one CTA per (b,c) row, register-resident ----------------
__device__ __forceinline__ float block_excl_scan10(float v, int tid) {
    __shared__ float ws[NWARPS];
    const int lane = tid & 31, wid = tid >> 5;
    float inc = v;
    #pragma unroll
    for (int off = 1; off < 32; off <<= 1) {
        float y = __shfl_up_sync(0xffffffffu, inc, off);
        if (lane >= off) inc += y;
    }
    if (lane == 31) ws[wid] = inc;
    __syncthreads();
    if (tid == 0) {
        float s = 0.f;
        #pragma unroll
        for (int w = 0; w < NWARPS; w++) { float t = ws[w]; ws[w] = s; s += t; }
    }
    __syncthreads();
    return ws[wid] + inc - v;
}

__global__ void __launch_bounds__(NTH)
ema_main_kernel(const float* __restrict__ x,
                const float* __restrict__ conv_w,
                const float* __restrict__ conv_b,
                float* __restrict__ out) {
    const int row = blockIdx.x;
    const int c   = row & (C_CH - 1);
    const int t   = threadIdx.x;
    const int i0  = t * CHUNK;

    const float* __restrict__ xr   = x   + (size_t)row * L_LEN;
    float*       __restrict__ outr = out + (size_t)row * L_LEN;

    // Load this thread's 20 contiguous elements into registers (5x LDG.128, aligned).
    float xv[CHUNK];
    {
        const float4* x4 = reinterpret_cast<const float4*>(xr + i0);
        #pragma unroll
        for (int g = 0; g < CHUNK / 4; g++) {
            float4 v = __ldg(x4 + g);
            xv[g*4+0] = v.x; xv[g*4+1] = v.y; xv[g*4+2] = v.z; xv[g*4+3] = v.w;
        }
    }
    // Conv neighbors (zero-padded at row ends); L1/L2 hits.
    const float leftN  = (t == 0)       ? 0.f : __ldg(xr + i0 - 1);
    const float rightN = (t == NTH - 1) ? 0.f : __ldg(xr + i0 + CHUNK);

    const float w0   = __ldg(&conv_w[c * 3 + 0]);
    const float w1   = __ldg(&conv_w[c * 3 + 1]);
    const float w2   = __ldg(&conv_w[c * 3 + 2]);
    const float bias = __ldg(&conv_b[c]);
    const float wstart = __ldg(&g_w0[t]);   // alpha * 0.9^i0

    // Phase A: chunk sum of weighted terms, weights by 0.9-recurrence (no table loads).
    float s = 0.f, w = wstart;
    #pragma unroll
    for (int k = 0; k < CHUNK; k++) {
        s = fmaf(xv[k], w, s);
        w *= 0.9f;
    }

    float run = block_excl_scan10(s, t);

    // Phase B: ema + depthwise conv + residual, 4-element groups -> immediate STG.128.
    w = wstart;
    float xp = leftN;
    #pragma unroll
    for (int g = 0; g < CHUNK / 4; g++) {
        float4 inv4 = __ldg(reinterpret_cast<const float4*>(&g_inv[i0 + g*4]));
        float iv[4] = {inv4.x, inv4.y, inv4.z, inv4.w};
        float o[4];
        #pragma unroll
        for (int q = 0; q < 4; q++) {
            const int k = g*4 + q;
            const float xc = xv[k];
            const float xn = (k == CHUNK - 1) ? rightN : xv[k + 1];
            run = fmaf(xc, w, run);
            w *= 0.9f;
            const float ema  = run * iv[q];
            const float conv = fmaf(w0, xp, fmaf(w1, xc, fmaf(w2, xn, bias)));
            o[q] = xc + ema + conv;
            xp = xc;
        }
        *reinterpret_cast<float4*>(outr + i0 + g*4) = make_float4(o[0], o[1], o[2], o[3]);
    }
}

extern "C" void kernel_launch(void* const* d_in, const int* in_sizes, int n_in,
                              void* d_out, int out_size) {
    const float* x      = (const float*)d_in[0];  // [16,256,80,80]
    const float* conv_w = (const float*)d_in[1];  // [256,1,3]
    const float* conv_b = (const float*)d_in[2];  // [256]
    float* out = (float*)d_out;

    ema_setup_kernel<<<1, SNTH>>>();
    ema_main_kernel<<<16 * C_CH, NTH>>>(x, conv_w, conv_b, out);
}

// round 3
// speedup vs baseline: 4.1524x; 1.0508x over previous
#include <cuda_runtime.h>

// Fixed shapes: B=16, C=256, H=W=80 -> L=6400 per (b,c) row, 4096 rows.
#define L_LEN    6400
#define NTH      800          // threads per row-CTA (25 warps)
#define CHUNK    8            // L_LEN / NTH, two float4 groups per thread
#define NWARPS   25
#define C_CH     256
#define ALPHA_F  0.1f
#define EPS_F    1e-7f

// Per-launch recomputed tables (__device__ globals = legal scratch).
__device__ float g_inv[L_LEN];   // 1 / (cumsum(alpha*0.9^j) + eps) via closed form
__device__ float g_w0[NTH];      // alpha * 0.9^(CHUNK*t) chunk-start anchors

// ---------------- setup: closed-form tables, fully parallel, no scan ----------------
// cumsum_{j<=i}(alpha*0.9^j) = 1 - 0.9^(i+1)   (geometric series, alpha = 1-0.9)
__global__ void ema_setup_kernel() {
    const int i = blockIdx.x * blockDim.x + threadIdx.x;
    if (i < L_LEN) {
        const float d = powf(0.9f, (float)(i + 1));
        g_inv[i] = 1.0f / ((1.0f + EPS_F) - d);
    }
    if (i < NTH)
        g_w0[i] = ALPHA_F * powf(0.9f, (float)(CHUNK * i));
}

// ---------------- main kernel: one CTA per (b,c) row, register-resident ----------------
__global__ void __launch_bounds__(NTH, 2)
ema_main_kernel(const float* __restrict__ x,
                const float* __restrict__ conv_w,
                const float* __restrict__ conv_b,
                float* __restrict__ out) {
    __shared__ float ws[NWARPS];

    const int row  = blockIdx.x;
    const int c    = row & (C_CH - 1);
    const int t    = threadIdx.x;
    const int lane = t & 31;
    const int wid  = t >> 5;
    const int i0   = t * CHUNK;

    const float* __restrict__ xr   = x   + (size_t)row * L_LEN;
    float*       __restrict__ outr = out + (size_t)row * L_LEN;

    // 8 contiguous elements -> registers (2x aligned LDG.128)
    float xv[CHUNK];
    {
        const float4* x4 = reinterpret_cast<const float4*>(xr + i0);
        float4 a = __ldg(x4 + 0);
        float4 b = __ldg(x4 + 1);
        xv[0]=a.x; xv[1]=a.y; xv[2]=a.z; xv[3]=a.w;
        xv[4]=b.x; xv[5]=b.y; xv[6]=b.z; xv[7]=b.w;
    }

    // Conv neighbors from adjacent threads' registers via shuffle; warp edges via LDG.
    float leftN  = __shfl_up_sync(0xffffffffu,  xv[CHUNK - 1], 1);
    float rightN = __shfl_down_sync(0xffffffffu, xv[0], 1);
    if (lane == 0)  leftN  = (t == 0)       ? 0.f : __ldg(xr + i0 - 1);
    if (lane == 31) rightN = (t == NTH - 1) ? 0.f : __ldg(xr + i0 + CHUNK);

    const float w0   = __ldg(&conv_w[c * 3 + 0]);
    const float w1   = __ldg(&conv_w[c * 3 + 1]);
    const float w2   = __ldg(&conv_w[c * 3 + 2]);
    const float bias = __ldg(&conv_b[c]);
    const float wstart = __ldg(&g_w0[t]);   // alpha * 0.9^i0

    // Phase A: chunk sum of weighted terms (weights via 0.9 recurrence, no loads)
    float s = 0.f, w = wstart;
    #pragma unroll
    for (int k = 0; k < CHUNK; k++) {
        s = fmaf(xv[k], w, s);
        w *= 0.9f;
    }

    // Block exclusive scan, ONE barrier: warp shfl-scan -> ws -> per-thread warp prefix
    float inc = s;
    #pragma unroll
    for (int off = 1; off < 32; off <<= 1) {
        float y = __shfl_up_sync(0xffffffffu, inc, off);
        if (lane >= off) inc += y;
    }
    if (lane == 31) ws[wid] = inc;
    __syncthreads();
    float prefix = 0.f;
    #pragma unroll
    for (int q = 0; q < NWARPS; q++) {
        float v = ws[q];                 // smem broadcast
        if (q < wid) prefix += v;
    }
    float run = prefix + inc - s;        // exclusive prefix for this thread

    // Phase B: ema + depthwise conv + residual; 4-wide groups -> STG.128
    w = wstart;
    float xp = leftN;
    #pragma unroll
    for (int g = 0; g < CHUNK / 4; g++) {
        const float4 inv4 = __ldg(reinterpret_cast<const float4*>(&g_inv[i0 + g*4]));
        const float iv[4] = {inv4.x, inv4.y, inv4.z, inv4.w};
        float o[4];
        #pragma unroll
        for (int q = 0; q < 4; q++) {
            const int k = g*4 + q;
            const float xc = xv[k];
            const float xn = (k == CHUNK - 1) ? rightN : xv[k + 1];
            run = fmaf(xc, w, run);
            w *= 0.9f;
            const float ema  = run * iv[q];
            const float conv = fmaf(w0, xp, fmaf(w1, xc, fmaf(w2, xn, bias)));
            o[q] = xc + ema + conv;
            xp = xc;
        }
        *reinterpret_cast<float4*>(outr + i0 + g*4) = make_float4(o[0], o[1], o[2], o[3]);
    }
}

extern "C" void kernel_launch(void* const* d_in, const int* in_sizes, int n_in,
                              void* d_out, int out_size) {
    const float* x      = (const float*)d_in[0];  // [16,256,80,80]
    const float* conv_w = (const float*)d_in[1];  // [256,1,3]
    const float* conv_b = (const float*)d_in[2];  // [256]
    float* out = (float*)d_out;

    ema_setup_kernel<<<(L_LEN + 255) / 256, 256>>>();
    ema_main_kernel<<<16 * C_CH, NTH>>>(x, conv_w, conv_b, out);
}